// round 1
// baseline (speedup 1.0000x reference)
#include <cuda_runtime.h>
#include <math.h>

#define NPERROW (512*512)            // 262144 elements per (b,c) row
#define NROWS   128                  // B*C
#define NTHREADS 1024
#define NBINS   16384                // top-14-bit histogram
#define BPT     (NBINS/NTHREADS)     // 16 bins per thread
#define CAP     4096                 // candidate buffer capacity per side

#define SMEM_BYTES (NBINS*4 + NTHREADS*4 + 2*CAP*4)   // 65536 + 4096 + 32768 = 102400

// monotone float -> uint key (ascending key == ascending float)
__device__ __forceinline__ unsigned int f2k(float f) {
    unsigned int u = __float_as_uint(f);
    unsigned int m = (unsigned int)((int)u >> 31) | 0x80000000u;
    return u ^ m;
}
__device__ __forceinline__ float k2f(unsigned int k) {
    unsigned int u = (k & 0x80000000u) ? (k ^ 0x80000000u) : ~k;
    return __uint_as_float(u);
}

__device__ void bitonic_sort(unsigned int* buf, int m, int tid) {
    // pad to power of two (m <= CAP)
    int P = 1024;
    while (P < m) P <<= 1;
    for (int i = m + tid; i < P; i += NTHREADS) buf[i] = 0xFFFFFFFFu;
    __syncthreads();
    for (int k = 2; k <= P; k <<= 1) {
        for (int j = k >> 1; j > 0; j >>= 1) {
            for (int i = tid; i < P; i += NTHREADS) {
                int ixj = i ^ j;
                if (ixj > i) {
                    unsigned int a = buf[i], b = buf[ixj];
                    bool up = ((i & k) == 0);
                    if ((a > b) == up) { buf[i] = b; buf[ixj] = a; }
                }
            }
            __syncthreads();
        }
    }
}

extern __shared__ unsigned int smem_u[];

__global__ __launch_bounds__(NTHREADS, 1)
void prox_kernel(const float* __restrict__ x,
                 const float* __restrict__ alpha_p,
                 const float* __restrict__ beta_p,
                 float* __restrict__ out)
{
    unsigned int* hist  = smem_u;            // NBINS
    unsigned int* aux   = hist + NBINS;      // NTHREADS
    unsigned int* bufLo = aux + NTHREADS;    // CAP
    unsigned int* bufHi = bufLo + CAP;       // CAP

    __shared__ unsigned int cntLo, cntHi;
    __shared__ int          binOf[4];
    __shared__ unsigned int preOf[4];
    __shared__ float        s_scale, s_t;

    const int tid = threadIdx.x;
    const int row = blockIdx.x;
    const float4* xr   = (const float4*)(x   + (size_t)row * NPERROW);
    float4*       outr = (float4*)      (out + (size_t)row * NPERROW);
    const int NV4 = NPERROW / 4;  // 65536

    // ---- init ----
    #pragma unroll
    for (int j = 0; j < BPT; j++) hist[tid + j * NTHREADS] = 0u;
    if (tid == 0) { cntLo = 0u; cntHi = 0u; }
    __syncthreads();

    // ---- Phase A: 14-bit histogram over the row ----
    for (int i = tid; i < NV4; i += NTHREADS) {
        float4 v = xr[i];
        atomicAdd(&hist[f2k(v.x) >> 18], 1u);
        atomicAdd(&hist[f2k(v.y) >> 18], 1u);
        atomicAdd(&hist[f2k(v.z) >> 18], 1u);
        atomicAdd(&hist[f2k(v.w) >> 18], 1u);
    }
    __syncthreads();

    // ---- Phase B: exclusive prefix over hist (per-thread serial + block scan) ----
    unsigned int loc[BPT];
    unsigned int s = 0;
    #pragma unroll
    for (int j = 0; j < BPT; j++) { loc[j] = hist[tid * BPT + j]; s += loc[j]; }
    aux[tid] = s;
    __syncthreads();
    for (int off = 1; off < NTHREADS; off <<= 1) {
        unsigned int v   = aux[tid];
        unsigned int add = (tid >= off) ? aux[tid - off] : 0u;
        __syncthreads();
        aux[tid] = v + add;
        __syncthreads();
    }
    unsigned int run = aux[tid] - s;   // exclusive prefix of this thread's chunk
    #pragma unroll
    for (int j = 0; j < BPT; j++) {
        unsigned int c = loc[j];
        hist[tid * BPT + j] = run;     // hist[b] := #elements with bin < b
        run += c;
    }
    __syncthreads();

    // ---- locate candidate bins for the 4 ranks ----
    // ranks (0-indexed ascending): floor/ceil neighbors of q*(N-1) for q=0.01, 0.99
    const unsigned int RANKS[4] = {2621u, 2622u, 259521u, 259522u};
    #pragma unroll
    for (int j = 0; j < BPT; j++) {
        int b = tid * BPT + j;
        unsigned int p  = hist[b];
        unsigned int nx = (b == NBINS - 1) ? (unsigned int)NPERROW : hist[b + 1];
        #pragma unroll
        for (int q = 0; q < 4; q++) {
            if (p <= RANKS[q] && RANKS[q] < nx) { binOf[q] = b; preOf[q] = p; }
        }
    }
    __syncthreads();

    const int bL0 = binOf[0], bL1 = binOf[1];
    const int bH0 = binOf[2], bH1 = binOf[3];

    // ---- Phase C: gather candidates (re-read row, expected mostly L2) ----
    for (int i = tid; i < NV4; i += NTHREADS) {
        float4 v = xr[i];
        unsigned int ks[4] = {f2k(v.x), f2k(v.y), f2k(v.z), f2k(v.w)};
        #pragma unroll
        for (int e = 0; e < 4; e++) {
            int d = (int)(ks[e] >> 18);
            if (d >= bL0 && d <= bL1) {
                unsigned int p = atomicAdd(&cntLo, 1u);
                if (p < CAP) bufLo[p] = ks[e];
            }
            if (d >= bH0 && d <= bH1) {
                unsigned int p = atomicAdd(&cntHi, 1u);
                if (p < CAP) bufHi[p] = ks[e];
            }
        }
    }
    __syncthreads();

    // ---- Phase D: sort tiny candidate sets, compute threshold ----
    int mLo = (int)min(cntLo, (unsigned int)CAP);
    int mHi = (int)min(cntHi, (unsigned int)CAP);
    bitonic_sort(bufLo, mLo, tid);
    bitonic_sort(bufHi, mHi, tid);
    __syncthreads();

    if (tid == 0) {
        unsigned int rl = RANKS[0] - preOf[0];   // rank within low buffer
        unsigned int rh = RANKS[2] - preOf[2];   // rank within high buffer
        double vlo0 = (double)k2f(bufLo[rl]);
        double vlo1 = (double)k2f(bufLo[rl + 1]);
        double vhi0 = (double)k2f(bufHi[rh]);
        double vhi1 = (double)k2f(bufHi[rh + 1]);

        double posLo = 0.01 * (double)(NPERROW - 1);
        double posHi = 0.99 * (double)(NPERROW - 1);
        double fracLo = posLo - (double)RANKS[0];
        double fracHi = posHi - (double)RANKS[2];

        double i1  = vlo0 + fracLo * (vlo1 - vlo0);
        double i99 = vhi0 + fracHi * (vhi1 - vhi0);

        float alpha = alpha_p[0];
        float beta  = beta_p[0];
        float th = (float)(i1 + (i99 - i1) * (double)alpha);
        float mask   = (th > 1e-14f) ? 1.0f : 0.0f;
        float th_new = th * mask + (1.0f - mask);
        s_scale = beta / th_new;
        s_t     = th * mask;
    }
    __syncthreads();

    // ---- Phase E: apply gate ----
    const float scale = s_scale;
    const float t     = s_t;
    for (int i = tid; i < NV4; i += NTHREADS) {
        float4 v = xr[i];
        float4 o;
        o.x = fmaxf(v.x, 0.0f) * (1.0f / (1.0f + __expf(-(scale * (fabsf(v.x) - t)))));
        o.y = fmaxf(v.y, 0.0f) * (1.0f / (1.0f + __expf(-(scale * (fabsf(v.y) - t)))));
        o.z = fmaxf(v.z, 0.0f) * (1.0f / (1.0f + __expf(-(scale * (fabsf(v.z) - t)))));
        o.w = fmaxf(v.w, 0.0f) * (1.0f / (1.0f + __expf(-(scale * (fabsf(v.w) - t)))));
        outr[i] = o;
    }
}

extern "C" void kernel_launch(void* const* d_in, const int* in_sizes, int n_in,
                              void* d_out, int out_size)
{
    const float* x     = (const float*)d_in[0];
    const float* alpha = (const float*)d_in[1];
    const float* beta  = (const float*)d_in[2];
    float* out = (float*)d_out;

    // idempotent, host-side, capture-safe; no statics/guards
    cudaFuncSetAttribute(prox_kernel, cudaFuncAttributeMaxDynamicSharedMemorySize, SMEM_BYTES);

    prox_kernel<<<NROWS, NTHREADS, SMEM_BYTES>>>(x, alpha, beta, out);
}